// round 10
// baseline (speedup 1.0000x reference)
#include <cuda_runtime.h>
#include <cuda_fp16.h>
#include <cstdint>

#define Bb 512
#define Tt 512
#define Ff 32
#define Hh 128
#define Ee 64
#define KPAD 200

__device__ uint32_t g_seq1[(size_t)Tt*Bb*Hh];   // layer-1 h packed (hi | lo<<16) fp16
__device__ int g_flag[64 * 2];                  // [group][rank] step counters

// L2-role dynamic smem layout
#define L2_WLO_BYTES (16*12*32*16)              // 98304
#define L2_BHI_OFF   L2_WLO_BYTES
#define L2_BLO_OFF   (L2_WLO_BYTES + 32*KPAD*2)
#define L2_DYN_BYTES (L2_WLO_BYTES + 2*32*KPAD*2)   // 123904

// ---------------- helpers ----------------
__device__ __forceinline__ uint32_t smem_u32(const void* p) {
    uint32_t a;
    asm("{ .reg .u64 t; cvta.to.shared.u64 t, %1; cvt.u32.u64 %0, t; }" : "=r"(a) : "l"(p));
    return a;
}
__device__ __forceinline__ void mma16816(float* d, const uint32_t* a, uint32_t b0, uint32_t b1) {
    asm("mma.sync.aligned.m16n8k16.row.col.f32.f16.f16.f32 "
        "{%0,%1,%2,%3}, {%4,%5,%6,%7}, {%8,%9}, {%0,%1,%2,%3};"
        : "+f"(d[0]), "+f"(d[1]), "+f"(d[2]), "+f"(d[3])
        : "r"(a[0]), "r"(a[1]), "r"(a[2]), "r"(a[3]), "r"(b0), "r"(b1));
}
__device__ __forceinline__ void splith(float v, __half& hi, __half& lo) {
    hi = __float2half_rn(v);
    lo = __float2half_rn(v - __half2float(hi));
}
__device__ __forceinline__ uint32_t pkh(__half a, __half b) {
    return (uint32_t)__half_as_ushort(a) | ((uint32_t)__half_as_ushort(b) << 16);
}
__device__ __forceinline__ void mbar_init(void* m, uint32_t cnt) {
    asm volatile("mbarrier.init.shared.b64 [%0], %1;" :: "r"(smem_u32(m)), "r"(cnt) : "memory");
}
__device__ __forceinline__ void mbar_wait(void* m, uint32_t parity) {
    uint32_t a = smem_u32(m), done;
    do {
        asm volatile("{\n\t.reg .pred p;\n\t"
            "mbarrier.try_wait.parity.acquire.cluster.shared::cta.b64 p, [%1], %2, 0x989680;\n\t"
            "selp.b32 %0, 1, 0, p;\n\t}" : "=r"(done) : "r"(a), "r"(parity) : "memory");
    } while (!done);
}
__device__ __forceinline__ uint32_t mapa_u32(uint32_t saddr, uint32_t peer) {
    uint32_t r;
    asm("mapa.shared::cluster.u32 %0, %1, %2;" : "=r"(r) : "r"(saddr), "r"(peer));
    return r;
}
__device__ __forceinline__ void st_release(int* p, int v) {
    asm volatile("st.release.gpu.s32 [%0], %1;" :: "l"(p), "r"(v) : "memory");
}
__device__ __forceinline__ int ld_acquire(const int* p) {
    int v;
    asm volatile("ld.acquire.gpu.s32 %0, [%1];" : "=r"(v) : "l"(p) : "memory");
    return v;
}
#define CLU_SYNC() do { asm volatile("barrier.cluster.arrive.aligned;" ::: "memory"); \
                        asm volatile("barrier.cluster.wait.aligned;" ::: "memory"); } while (0)

__device__ __forceinline__ float sigm(float z) { return __fdividef(1.0f, 1.0f + __expf(-z)); }
__device__ __forceinline__ float tanh_(float z) {
    float e = __expf(2.0f * z);
    return 1.0f - __fdividef(2.0f, e + 1.0f);
}

__global__ void flags_reset_k() {
    if (threadIdx.x < 128) g_flag[threadIdx.x] = 0;
}

// ---------------------------------------------------------------------------
// Fused kernel: blocks 0..127 = layer-1 role (clusters of 2, as R9);
// blocks 128..143 = layer-2 role (32 batch rows each), consuming g_seq1 via
// per-step release/acquire flags.
// ---------------------------------------------------------------------------
__global__ void __launch_bounds__(512, 1) __cluster_dims__(2, 1, 1)
fused_lstm(const float* __restrict__ x,
           const float* __restrict__ Wih1, const float* __restrict__ Whh1,
           const float* __restrict__ bih1, const float* __restrict__ bhh1,
           const float* __restrict__ Wih2, const float* __restrict__ Whh2,
           const float* __restrict__ bih2, const float* __restrict__ bhh2,
           float* __restrict__ out)
{
    extern __shared__ char dyn[];
    const int tid = threadIdx.x;
    const int lane = tid & 31, warp = tid >> 5;
    const int tg = lane & 3, gid = lane >> 2;
    const int q = gid >> 2, m = gid & 3;

    if (blockIdx.x < 128) {
        // ================= LAYER 1 ROLE (R9 + flag store) =================
        __shared__ __half Bhi[2][8][KPAD];
        __shared__ __half Blo[2][8][KPAD];
        __shared__ alignas(8) unsigned long long mbar[2];

        uint32_t rank;
        asm("mov.u32 %0, %%cluster_ctarank;" : "=r"(rank));
        const int grp = blockIdx.x >> 1;
        const int r0 = grp * 8;
        const int U0 = (int)rank * 64;

        for (int i = tid; i < 2 * 8 * KPAD; i += 512) {
            (&Bhi[0][0][0])[i] = __ushort_as_half(0);
            (&Blo[0][0][0])[i] = __ushort_as_half(0);
        }

        uint32_t Ahi[10][4], Alo[10][4];
#pragma unroll
        for (int kf = 0; kf < 10; kf++) {
            int k0 = kf * 16 + tg * 2;
#pragma unroll
            for (int qq = 0; qq < 4; qq++) {
                int rslot = gid + (qq & 1) * 8;
                int kk = k0 + (qq >> 1) * 8;
                int ul = warp * 4 + (rslot & 3);
                int gate = 2 * (rslot >> 3) + ((rslot >> 2) & 1);
                int R = gate * Hh + U0 + ul;
                float w0 = (kk < Hh) ? Whh1[R * Hh + kk] : Wih1[R * Ff + (kk - Hh)];
                float w1 = (kk + 1 < Hh) ? Whh1[R * Hh + kk + 1] : Wih1[R * Ff + (kk + 1 - Hh)];
                __half h0, l0, h1, l1;
                splith(w0, h0, l0);
                splith(w1, h1, l1);
                Ahi[kf][qq] = pkh(h0, h1);
                Alo[kf][qq] = pkh(l0, l1);
            }
        }

        const int u = U0 + warp * 4 + m;
        const int c = tg * 2 + q;
        const float bi_ = bih1[u] + bhh1[u];
        const float bf_ = bih1[Hh + u] + bhh1[Hh + u];
        const float bg_ = bih1[2 * Hh + u] + bhh1[2 * Hh + u];
        const float bo_ = bih1[3 * Hh + u] + bhh1[3 * Hh + u];

        if (tid == 0) { mbar_init(&mbar[0], 32); mbar_init(&mbar[1], 32); }
        __syncthreads();

        uint32_t cp_lhi = 0, cp_llo = 0, cp_rhi = 0, cp_rlo = 0, rmb = 0;
        if (tid < 32) {
            uint32_t off = (uint32_t)(((tid >> 3) & 3) * (KPAD * 2) + U0 * 2 + (tid & 7) * 16);
            cp_lhi = smem_u32(&Bhi[0][0][0]) + off;
            cp_llo = smem_u32(&Blo[0][0][0]) + off;
            cp_rhi = mapa_u32(cp_lhi, rank ^ 1u);
            cp_rlo = mapa_u32(cp_llo, rank ^ 1u);
            rmb    = mapa_u32(smem_u32(&mbar[0]), rank ^ 1u);
        }

        const int xb = tid >> 5, xf = tid & 31;
        float xn = 0.0f;
        if (tid < 256) {
            float x0 = x[((size_t)(r0 + xb) * Tt + 0) * Ff + xf];
            __half xh, xl;
            splith(x0, xh, xl);
            Bhi[0][xb][Hh + xf] = xh;
            Blo[0][xb][Hh + xf] = xl;
            xn = x[((size_t)(r0 + xb) * Tt + 1) * Ff + xf];
        }
        __syncthreads();
        CLU_SYNC();

        float cst = 0.0f;
        int ph0 = 0, ph1 = 0;
        const int boffw = gid * KPAD + tg * 2;

        for (int t = 0; t < Tt; t++) {
            const int cur = t & 1;
            if (t > 0) {
                if (cur == 0) { mbar_wait(&mbar[0], (uint32_t)ph0); ph0 ^= 1; }
                else          { mbar_wait(&mbar[1], (uint32_t)ph1); ph1 ^= 1; }
            }

            float dh[4] = {0.f,0.f,0.f,0.f}, dm[4] = {0.f,0.f,0.f,0.f}, dl[4] = {0.f,0.f,0.f,0.f};
            const __half* bh = &Bhi[cur][0][0];
            const __half* bl = &Blo[cur][0][0];
#pragma unroll
            for (int kf = 0; kf < 10; kf++) {
                uint32_t b0 = *(const uint32_t*)(bh + boffw + kf * 16);
                uint32_t b1 = *(const uint32_t*)(bh + boffw + kf * 16 + 8);
                uint32_t c0 = *(const uint32_t*)(bl + boffw + kf * 16);
                uint32_t c1 = *(const uint32_t*)(bl + boffw + kf * 16 + 8);
                mma16816(dh, Ahi[kf], b0, b1);
                mma16816(dm, Alo[kf], b0, b1);
                mma16816(dl, Ahi[kf], c0, c1);
            }
            float d0 = dh[0] + dm[0] + dl[0];
            float d1 = dh[1] + dm[1] + dl[1];
            float d2 = dh[2] + dm[2] + dl[2];
            float d3 = dh[3] + dm[3] + dl[3];

            float X = __shfl_xor_sync(0xFFFFFFFFu, q ? d0 : d1, 16);
            float Y = __shfl_xor_sync(0xFFFFFFFFu, q ? d2 : d3, 16);
            float zi = (q ? X : d0) + bi_;
            float zf = (q ? d1 : X) + bf_;
            float zg = (q ? Y : d2) + bg_;
            float zo = (q ? d3 : Y) + bo_;

            cst = sigm(zf) * cst + sigm(zi) * tanh_(zg);
            float h = sigm(zo) * tanh_(cst);
            __half hh, hl;
            splith(h, hh, hl);
            g_seq1[((size_t)t * Bb + r0 + c) * Hh + u] = pkh(hh, hl);

            const int nb = cur ^ 1;
            if (t + 1 < Tt) {
                Bhi[nb][c][u] = hh;
                Blo[nb][c][u] = hl;
                if (tid < 256) {
                    __half xh, xl;
                    splith(xn, xh, xl);
                    Bhi[nb][xb][Hh + xf] = xh;
                    Blo[nb][xb][Hh + xf] = xl;
                    xn = (t + 2 < Tt) ? x[((size_t)(r0 + xb) * Tt + t + 2) * Ff + xf] : 0.0f;
                }
            }
            __syncthreads();

            // publish step t to layer-2 consumers (all STGs ordered by the sync)
            if (tid == 64) st_release(&g_flag[grp * 2 + (int)rank], t + 1);

            if (t + 1 < Tt && tid < 32) {
                const uint32_t bo_ofs = (uint32_t)nb * (uint32_t)(8 * KPAD * 2);
#pragma unroll
                for (int i = 0; i < 4; i++) {
                    uint32_t la = ((i >> 1) ? cp_llo : cp_lhi) + bo_ofs + (uint32_t)((i & 1) * 4 * KPAD * 2);
                    uint32_t ra = ((i >> 1) ? cp_rlo : cp_rhi) + bo_ofs + (uint32_t)((i & 1) * 4 * KPAD * 2);
                    uint32_t v0, v1, v2, v3;
                    asm volatile("ld.shared.v4.u32 {%0,%1,%2,%3}, [%4];"
                        : "=r"(v0), "=r"(v1), "=r"(v2), "=r"(v3) : "r"(la));
                    unsigned long long p0, p1;
                    asm("mov.b64 %0, {%1, %2};" : "=l"(p0) : "r"(v0), "r"(v1));
                    asm("mov.b64 %0, {%1, %2};" : "=l"(p1) : "r"(v2), "r"(v3));
                    asm volatile("st.shared::cluster.b64 [%0], %1;" :: "r"(ra), "l"(p0) : "memory");
                    asm volatile("st.shared::cluster.b64 [%0], %1;" :: "r"(ra + 8), "l"(p1) : "memory");
                }
                asm volatile("mbarrier.arrive.release.cluster.shared::cluster.b64 _, [%0];"
                    :: "r"(rmb + (uint32_t)nb * 8) : "memory");
            }
        }
        CLU_SYNC();
    } else {
        // ================= LAYER 2 ROLE (16 CTAs x 32 batch) =================
        const int cta2 = blockIdx.x - 128;
        const int r0 = cta2 * 32;
        const int g0 = cta2 * 4;       // 4 producer groups -> 8 flags

        char*   wloP = dyn;
        __half* B2hi = (__half*)(dyn + L2_BHI_OFF);
        __half* B2lo = (__half*)(dyn + L2_BLO_OFF);

        // W-hi fragments in registers; W-lo fragments in smem (per-thread layout)
        uint32_t Ahi2[12][4];
#pragma unroll
        for (int kf = 0; kf < 12; kf++) {
            int k0 = kf * 16 + tg * 2;
            uint32_t lo4[4];
#pragma unroll
            for (int qq = 0; qq < 4; qq++) {
                int rslot = gid + (qq & 1) * 8;
                int kk = k0 + (qq >> 1) * 8;
                int ul = warp * 4 + (rslot & 3);
                int gate = 2 * (rslot >> 3) + ((rslot >> 2) & 1);
                int R = gate * Ee + ul;
                float w0 = (kk < Hh) ? Wih2[R * Hh + kk] : Whh2[R * Ee + (kk - Hh)];
                float w1 = (kk + 1 < Hh) ? Wih2[R * Hh + kk + 1] : Whh2[R * Ee + (kk + 1 - Hh)];
                __half h0, l0, h1, l1;
                splith(w0, h0, l0);
                splith(w1, h1, l1);
                Ahi2[kf][qq] = pkh(h0, h1);
                lo4[qq] = pkh(l0, l1);
            }
            *(uint4*)(wloP + (size_t)((warp * 12 + kf) * 32 + lane) * 16) =
                make_uint4(lo4[0], lo4[1], lo4[2], lo4[3]);
        }

        const int u = warp * 4 + m;
        const int cbase = tg * 2 + q;
        const float bi_ = bih2[u] + bhh2[u];
        const float bf_ = bih2[Ee + u] + bhh2[Ee + u];
        const float bg_ = bih2[2 * Ee + u] + bhh2[2 * Ee + u];
        const float bo_ = bih2[3 * Ee + u] + bhh2[3 * Ee + u];

        const int lk = tid & 127, cb = tid >> 7;
        float cst[4] = {0.f, 0.f, 0.f, 0.f};
        float hl4[4] = {0.f, 0.f, 0.f, 0.f};

        for (int t = 0; t < Tt; t++) {
            // wait for all 8 producer CTAs of our 32 batch rows
            if (tid < 8) {
                const int* fp = &g_flag[g0 * 2 + tid];
                while (ld_acquire(fp) < t + 1) { }
            }
            __syncthreads();

            // fill B: h1 from g_seq1 (8 packed u32 per thread, coalesced)
#pragma unroll
            for (int i = 0; i < 8; i++) {
                int col = cb + i * 4;
                uint32_t v = g_seq1[((size_t)t * Bb + r0 + col) * Hh + lk];
                B2hi[col * KPAD + lk] = __ushort_as_half((uint16_t)(v & 0xFFFF));
                B2lo[col * KPAD + lk] = __ushort_as_half((uint16_t)(v >> 16));
            }
            // fill B: h2 from previous step's cells (zeros at t=0)
#pragma unroll
            for (int nt = 0; nt < 4; nt++) {
                int col = nt * 8 + cbase;
                __half hh, hlw;
                splith(hl4[nt], hh, hlw);
                B2hi[col * KPAD + Hh + u] = hh;
                B2lo[col * KPAD + Hh + u] = hlw;
            }
            __syncthreads();

#pragma unroll
            for (int nt = 0; nt < 4; nt++) {
                float dh[4] = {0.f,0.f,0.f,0.f}, dm[4] = {0.f,0.f,0.f,0.f}, dl[4] = {0.f,0.f,0.f,0.f};
                const __half* bh = B2hi + (nt * 8 + gid) * KPAD + tg * 2;
                const __half* bl = B2lo + (nt * 8 + gid) * KPAD + tg * 2;
#pragma unroll
                for (int kf = 0; kf < 12; kf++) {
                    uint4 a4 = *(const uint4*)(wloP + (size_t)((warp * 12 + kf) * 32 + lane) * 16);
                    uint32_t al[4] = {a4.x, a4.y, a4.z, a4.w};
                    uint32_t b0 = *(const uint32_t*)(bh + kf * 16);
                    uint32_t b1 = *(const uint32_t*)(bh + kf * 16 + 8);
                    uint32_t c0 = *(const uint32_t*)(bl + kf * 16);
                    uint32_t c1 = *(const uint32_t*)(bl + kf * 16 + 8);
                    mma16816(dh, Ahi2[kf], b0, b1);
                    mma16816(dm, Ahi2[kf], c0, c1);
                    mma16816(dl, al, b0, b1);
                }
                float d0 = dh[0] + dm[0] + dl[0];
                float d1 = dh[1] + dm[1] + dl[1];
                float d2 = dh[2] + dm[2] + dl[2];
                float d3 = dh[3] + dm[3] + dl[3];

                float X = __shfl_xor_sync(0xFFFFFFFFu, q ? d0 : d1, 16);
                float Y = __shfl_xor_sync(0xFFFFFFFFu, q ? d2 : d3, 16);
                float zi = (q ? X : d0) + bi_;
                float zf = (q ? d1 : X) + bf_;
                float zg = (q ? Y : d2) + bg_;
                float zo = (q ? d3 : Y) + bo_;

                cst[nt] = sigm(zf) * cst[nt] + sigm(zi) * tanh_(zg);
                hl4[nt] = sigm(zo) * tanh_(cst[nt]);
            }
            // no end-of-loop sync needed: next iteration's fill is gated by the
            // top-of-loop barrier, which no thread passes before finishing MMAs.
        }

#pragma unroll
        for (int nt = 0; nt < 4; nt++)
            out[(size_t)(r0 + nt * 8 + cbase) * Ee + u] = hl4[nt];
    }
}

extern "C" void kernel_launch(void* const* d_in, const int* in_sizes, int n_in,
                              void* d_out, int out_size)
{
    const float* x    = (const float*)d_in[0];
    const float* Wih1 = (const float*)d_in[1];
    const float* Whh1 = (const float*)d_in[2];
    const float* bih1 = (const float*)d_in[3];
    const float* bhh1 = (const float*)d_in[4];
    const float* Wih2 = (const float*)d_in[5];
    const float* Whh2 = (const float*)d_in[6];
    const float* bih2 = (const float*)d_in[7];
    const float* bhh2 = (const float*)d_in[8];
    float* out = (float*)d_out;

    cudaFuncSetAttribute(fused_lstm, cudaFuncAttributeMaxDynamicSharedMemorySize, L2_DYN_BYTES);

    flags_reset_k<<<1, 128>>>();
    fused_lstm<<<144, 512, L2_DYN_BYTES>>>(x, Wih1, Whh1, bih1, bhh1,
                                           Wih2, Whh2, bih2, bhh2, out);
}

// round 11
// speedup vs baseline: 1.7188x; 1.7188x over previous
#include <cuda_runtime.h>
#include <cuda_fp16.h>
#include <cstdint>

#define Bb 512
#define Tt 512
#define Ff 32
#define Hh 128
#define Ee 64
#define KPAD 200

__device__ uint32_t g_seq1[(size_t)Tt*Bb*Hh];   // layer-1 h packed (hi | lo<<16) fp16

// ---------------- helpers ----------------
__device__ __forceinline__ uint32_t smem_u32(const void* p) {
    uint32_t a;
    asm("{ .reg .u64 t; cvta.to.shared.u64 t, %1; cvt.u32.u64 %0, t; }" : "=r"(a) : "l"(p));
    return a;
}
__device__ __forceinline__ void mma16816(float* d, const uint32_t* a, uint32_t b0, uint32_t b1) {
    asm("mma.sync.aligned.m16n8k16.row.col.f32.f16.f16.f32 "
        "{%0,%1,%2,%3}, {%4,%5,%6,%7}, {%8,%9}, {%0,%1,%2,%3};"
        : "+f"(d[0]), "+f"(d[1]), "+f"(d[2]), "+f"(d[3])
        : "r"(a[0]), "r"(a[1]), "r"(a[2]), "r"(a[3]), "r"(b0), "r"(b1));
}
__device__ __forceinline__ void splith(float v, __half& hi, __half& lo) {
    hi = __float2half_rn(v);
    lo = __float2half_rn(v - __half2float(hi));
}
__device__ __forceinline__ uint32_t pkh(__half a, __half b) {
    return (uint32_t)__half_as_ushort(a) | ((uint32_t)__half_as_ushort(b) << 16);
}
__device__ __forceinline__ void mbar_init(void* m, uint32_t cnt) {
    asm volatile("mbarrier.init.shared.b64 [%0], %1;" :: "r"(smem_u32(m)), "r"(cnt) : "memory");
}
__device__ __forceinline__ void mbar_wait(void* m, uint32_t parity) {
    uint32_t a = smem_u32(m), done;
    do {
        asm volatile("{\n\t.reg .pred p;\n\t"
            "mbarrier.try_wait.parity.acquire.cluster.shared::cta.b64 p, [%1], %2, 0x989680;\n\t"
            "selp.b32 %0, 1, 0, p;\n\t}" : "=r"(done) : "r"(a), "r"(parity) : "memory");
    } while (!done);
}
__device__ __forceinline__ uint32_t mapa_u32(uint32_t saddr, uint32_t peer) {
    uint32_t r;
    asm("mapa.shared::cluster.u32 %0, %1, %2;" : "=r"(r) : "r"(saddr), "r"(peer));
    return r;
}
#define CLU_SYNC() do { asm volatile("barrier.cluster.arrive.aligned;" ::: "memory"); \
                        asm volatile("barrier.cluster.wait.aligned;" ::: "memory"); } while (0)

__device__ __forceinline__ float sigm(float z) { return __fdividef(1.0f, 1.0f + __expf(-z)); }
__device__ __forceinline__ float tanh_(float z) {
    float e = __expf(2.0f * z);
    return 1.0f - __fdividef(2.0f, e + 1.0f);
}

// ---------------------------------------------------------------------------
// Layer 1: 64 clusters x 2 CTAs x 512 threads. Cluster = 8 batch rows.
// CTA rank owns hidden units U0..U0+63 (all 4 gates). K: 0..127 h, 128..159 x.
// Exchange hidden: per step, MMAs over LOCAL K-frags (own units + x) issue
// first; mbar_wait for the peer's DSMEM copy lands between them and the 4
// peer K-frags, so copy latency overlaps local MMA work.
// ---------------------------------------------------------------------------
__global__ void __launch_bounds__(512, 1) __cluster_dims__(2, 1, 1)
lstm1_mma(const float* __restrict__ x,
          const float* __restrict__ Wih, const float* __restrict__ Whh,
          const float* __restrict__ bih, const float* __restrict__ bhh)
{
    __shared__ __half Bhi[2][8][KPAD];
    __shared__ __half Blo[2][8][KPAD];
    __shared__ alignas(8) unsigned long long mbar[2];

    const int tid = threadIdx.x;
    uint32_t rank;
    asm("mov.u32 %0, %%cluster_ctarank;" : "=r"(rank));
    const int r0 = (blockIdx.x >> 1) * 8;
    const int U0 = (int)rank * 64;
    const int lane = tid & 31, warp = tid >> 5;
    const int tg = lane & 3, gid = lane >> 2;
    const int q = gid >> 2, m = gid & 3;
    const int kf_own = (int)rank * 4;        // own-units K-frags: kf_own..kf_own+3
    const int kf_peer = 4 - kf_own;          // peer K-frags: kf_peer..kf_peer+3

    for (int i = tid; i < 2 * 8 * KPAD; i += 512) {
        (&Bhi[0][0][0])[i] = __ushort_as_half(0);
        (&Blo[0][0][0])[i] = __ushort_as_half(0);
    }

    // register weight fragments with permuted rows
    uint32_t Ahi[10][4], Alo[10][4];
#pragma unroll
    for (int kf = 0; kf < 10; kf++) {
        int k0 = kf * 16 + tg * 2;
#pragma unroll
        for (int qq = 0; qq < 4; qq++) {
            int rslot = gid + (qq & 1) * 8;
            int kk = k0 + (qq >> 1) * 8;
            int ul = warp * 4 + (rslot & 3);
            int gate = 2 * (rslot >> 3) + ((rslot >> 2) & 1);
            int R = gate * Hh + U0 + ul;
            float w0 = (kk < Hh) ? Whh[R * Hh + kk] : Wih[R * Ff + (kk - Hh)];
            float w1 = (kk + 1 < Hh) ? Whh[R * Hh + kk + 1] : Wih[R * Ff + (kk + 1 - Hh)];
            __half h0, l0, h1, l1;
            splith(w0, h0, l0);
            splith(w1, h1, l1);
            Ahi[kf][qq] = pkh(h0, h1);
            Alo[kf][qq] = pkh(l0, l1);
        }
    }

    // this thread's cell: unit u (global), batch col c
    const int u = U0 + warp * 4 + m;
    const int c = tg * 2 + q;
    const float bi_ = bih[u] + bhh[u];
    const float bf_ = bih[Hh + u] + bhh[Hh + u];
    const float bg_ = bih[2 * Hh + u] + bhh[2 * Hh + u];
    const float bo_ = bih[3 * Hh + u] + bhh[3 * Hh + u];

    if (tid == 0) { mbar_init(&mbar[0], 32); mbar_init(&mbar[1], 32); }
    __syncthreads();

    // copier (warp 0) addresses: own-units region, 2 KB total, 16B chunks
    uint32_t cp_lhi = 0, cp_llo = 0, cp_rhi = 0, cp_rlo = 0, rmb = 0;
    if (tid < 32) {
        uint32_t off = (uint32_t)(((tid >> 3) & 3) * (KPAD * 2) + U0 * 2 + (tid & 7) * 16);
        cp_lhi = smem_u32(&Bhi[0][0][0]) + off;
        cp_llo = smem_u32(&Blo[0][0][0]) + off;
        cp_rhi = mapa_u32(cp_lhi, rank ^ 1u);
        cp_rlo = mapa_u32(cp_llo, rank ^ 1u);
        rmb    = mapa_u32(smem_u32(&mbar[0]), rank ^ 1u);
    }

    const int xb = tid >> 5, xf = tid & 31;
    float xn = 0.0f;
    if (tid < 256) {
        float x0 = x[((size_t)(r0 + xb) * Tt + 0) * Ff + xf];
        __half xh, xl;
        splith(x0, xh, xl);
        Bhi[0][xb][Hh + xf] = xh;
        Blo[0][xb][Hh + xf] = xl;
        xn = x[((size_t)(r0 + xb) * Tt + 1) * Ff + xf];
    }
    __syncthreads();
    CLU_SYNC();   // mbar init + initial buffers visible cluster-wide

    float cst = 0.0f;
    int ph0 = 0, ph1 = 0;
    const int boffw = gid * KPAD + tg * 2;

    for (int t = 0; t < Tt; t++) {
        const int cur = t & 1;

        float dh[4] = {0.f,0.f,0.f,0.f}, dm[4] = {0.f,0.f,0.f,0.f}, dl[4] = {0.f,0.f,0.f,0.f};
        const __half* bh = &Bhi[cur][0][0];
        const __half* bl = &Blo[cur][0][0];

        // ---- local K-frags first: own units (4) + x (2) — no peer dependency
#pragma unroll
        for (int i = 0; i < 6; i++) {
            const int kf = (i < 4) ? (kf_own + i) : (8 + (i - 4));
            uint32_t b0 = *(const uint32_t*)(bh + boffw + kf * 16);
            uint32_t b1 = *(const uint32_t*)(bh + boffw + kf * 16 + 8);
            uint32_t c0 = *(const uint32_t*)(bl + boffw + kf * 16);
            uint32_t c1 = *(const uint32_t*)(bl + boffw + kf * 16 + 8);
            mma16816(dh, Ahi[kf], b0, b1);
            mma16816(dm, Alo[kf], b0, b1);
            mma16816(dl, Ahi[kf], c0, c1);
        }

        // ---- wait for peer copy of this buffer, then peer K-frags (4)
        if (t > 0) {
            if (cur == 0) { mbar_wait(&mbar[0], (uint32_t)ph0); ph0 ^= 1; }
            else          { mbar_wait(&mbar[1], (uint32_t)ph1); ph1 ^= 1; }
        }
#pragma unroll
        for (int i = 0; i < 4; i++) {
            const int kf = kf_peer + i;
            uint32_t b0 = *(const uint32_t*)(bh + boffw + kf * 16);
            uint32_t b1 = *(const uint32_t*)(bh + boffw + kf * 16 + 8);
            uint32_t c0 = *(const uint32_t*)(bl + boffw + kf * 16);
            uint32_t c1 = *(const uint32_t*)(bl + boffw + kf * 16 + 8);
            mma16816(dh, Ahi[kf], b0, b1);
            mma16816(dm, Alo[kf], b0, b1);
            mma16816(dl, Ahi[kf], c0, c1);
        }

        float d0 = dh[0] + dm[0] + dl[0];
        float d1 = dh[1] + dm[1] + dl[1];
        float d2 = dh[2] + dm[2] + dl[2];
        float d3 = dh[3] + dm[3] + dl[3];

        float X = __shfl_xor_sync(0xFFFFFFFFu, q ? d0 : d1, 16);
        float Y = __shfl_xor_sync(0xFFFFFFFFu, q ? d2 : d3, 16);
        float zi = (q ? X : d0) + bi_;
        float zf = (q ? d1 : X) + bf_;
        float zg = (q ? Y : d2) + bg_;
        float zo = (q ? d3 : Y) + bo_;

        cst = sigm(zf) * cst + sigm(zi) * tanh_(zg);
        float h = sigm(zo) * tanh_(cst);
        __half hh, hl;
        splith(h, hh, hl);
        g_seq1[((size_t)t * Bb + r0 + c) * Hh + u] = pkh(hh, hl);

        const int nb = cur ^ 1;
        if (t + 1 < Tt) {
            // local staging only
            Bhi[nb][c][u] = hh;
            Blo[nb][c][u] = hl;
            if (tid < 256) {
                __half xh, xl;
                splith(xn, xh, xl);
                Bhi[nb][xb][Hh + xf] = xh;
                Blo[nb][xb][Hh + xf] = xl;
                xn = (t + 2 < Tt) ? x[((size_t)(r0 + xb) * Tt + t + 2) * Ff + xf] : 0.0f;
            }
        }
        __syncthreads();

        if (t + 1 < Tt && tid < 32) {
            const uint32_t bo_ofs = (uint32_t)nb * (uint32_t)(8 * KPAD * 2);
#pragma unroll
            for (int i = 0; i < 4; i++) {
                uint32_t la = ((i >> 1) ? cp_llo : cp_lhi) + bo_ofs + (uint32_t)((i & 1) * 4 * KPAD * 2);
                uint32_t ra = ((i >> 1) ? cp_rlo : cp_rhi) + bo_ofs + (uint32_t)((i & 1) * 4 * KPAD * 2);
                uint32_t v0, v1, v2, v3;
                asm volatile("ld.shared.v4.u32 {%0,%1,%2,%3}, [%4];"
                    : "=r"(v0), "=r"(v1), "=r"(v2), "=r"(v3) : "r"(la));
                unsigned long long p0, p1;
                asm("mov.b64 %0, {%1, %2};" : "=l"(p0) : "r"(v0), "r"(v1));
                asm("mov.b64 %0, {%1, %2};" : "=l"(p1) : "r"(v2), "r"(v3));
                asm volatile("st.shared::cluster.b64 [%0], %1;" :: "r"(ra), "l"(p0) : "memory");
                asm volatile("st.shared::cluster.b64 [%0], %1;" :: "r"(ra + 8), "l"(p1) : "memory");
            }
            asm volatile("mbarrier.arrive.release.cluster.shared::cluster.b64 _, [%0];"
                :: "r"(rmb + (uint32_t)nb * 8) : "memory");
        }
    }
    CLU_SYNC();   // no CTA exits while peer stores may be in flight
}

// ---------------------------------------------------------------------------
// Layer 2: 64 blocks x 512 threads. M=256 gate rows (permuted), K=192
// (0..127 h1 from g_seq1, 128..191 h2). Identical to R9.
// ---------------------------------------------------------------------------
__global__ void __launch_bounds__(512, 1)
lstm2_mma(const float* __restrict__ Wih, const float* __restrict__ Whh,
          const float* __restrict__ bih, const float* __restrict__ bhh,
          float* __restrict__ out)
{
    __shared__ __half Bhi[2][8][KPAD];
    __shared__ __half Blo[2][8][KPAD];

    const int tid = threadIdx.x;
    const int r0 = blockIdx.x * 8;
    const int lane = tid & 31, warp = tid >> 5;
    const int tg = lane & 3, gid = lane >> 2;
    const int q = gid >> 2, m = gid & 3;

    for (int i = tid; i < 2 * 8 * KPAD; i += 512) {
        (&Bhi[0][0][0])[i] = __ushort_as_half(0);
        (&Blo[0][0][0])[i] = __ushort_as_half(0);
    }

    uint32_t Ahi[12][4], Alo[12][4];
#pragma unroll
    for (int kf = 0; kf < 12; kf++) {
        int k0 = kf * 16 + tg * 2;
#pragma unroll
        for (int qq = 0; qq < 4; qq++) {
            int rslot = gid + (qq & 1) * 8;
            int kk = k0 + (qq >> 1) * 8;
            int ul = warp * 4 + (rslot & 3);
            int gate = 2 * (rslot >> 3) + ((rslot >> 2) & 1);
            int R = gate * Ee + ul;
            float w0 = (kk < Hh) ? Wih[R * Hh + kk] : Whh[R * Ee + (kk - Hh)];
            float w1 = (kk + 1 < Hh) ? Wih[R * Hh + kk + 1] : Whh[R * Ee + (kk + 1 - Hh)];
            __half h0, l0, h1, l1;
            splith(w0, h0, l0);
            splith(w1, h1, l1);
            Ahi[kf][qq] = pkh(h0, h1);
            Alo[kf][qq] = pkh(l0, l1);
        }
    }

    const int u = warp * 4 + m;
    const int c = tg * 2 + q;
    const float bi_ = bih[u] + bhh[u];
    const float bf_ = bih[Ee + u] + bhh[Ee + u];
    const float bg_ = bih[2 * Ee + u] + bhh[2 * Ee + u];
    const float bo_ = bih[3 * Ee + u] + bhh[3 * Ee + u];

    const int lk = tid & 127, lb = tid >> 7;
    __syncthreads();
    uint32_t p0 = g_seq1[((size_t)0 * Bb + r0 + lb) * Hh + lk];
    uint32_t p1 = g_seq1[((size_t)0 * Bb + r0 + lb + 4) * Hh + lk];
    Bhi[0][lb][lk]     = __ushort_as_half((uint16_t)(p0 & 0xFFFF));
    Blo[0][lb][lk]     = __ushort_as_half((uint16_t)(p0 >> 16));
    Bhi[0][lb + 4][lk] = __ushort_as_half((uint16_t)(p1 & 0xFFFF));
    Blo[0][lb + 4][lk] = __ushort_as_half((uint16_t)(p1 >> 16));
    p0 = g_seq1[((size_t)1 * Bb + r0 + lb) * Hh + lk];
    p1 = g_seq1[((size_t)1 * Bb + r0 + lb + 4) * Hh + lk];
    __syncthreads();

    float cst = 0.0f, hlast = 0.0f;
    const int boffw = gid * KPAD + tg * 2;

    for (int t = 0; t < Tt; t++) {
        const int cur = t & 1;
        float dh[4] = {0.f,0.f,0.f,0.f}, dm[4] = {0.f,0.f,0.f,0.f}, dl[4] = {0.f,0.f,0.f,0.f};
        const __half* bh = &Bhi[cur][0][0];
        const __half* bl = &Blo[cur][0][0];
#pragma unroll
        for (int kf = 0; kf < 12; kf++) {
            uint32_t b0 = *(const uint32_t*)(bh + boffw + kf * 16);
            uint32_t b1 = *(const uint32_t*)(bh + boffw + kf * 16 + 8);
            uint32_t c0 = *(const uint32_t*)(bl + boffw + kf * 16);
            uint32_t c1 = *(const uint32_t*)(bl + boffw + kf * 16 + 8);
            mma16816(dh, Ahi[kf], b0, b1);
            mma16816(dm, Alo[kf], b0, b1);
            mma16816(dl, Ahi[kf], c0, c1);
        }
        float d0 = dh[0] + dm[0] + dl[0];
        float d1 = dh[1] + dm[1] + dl[1];
        float d2 = dh[2] + dm[2] + dl[2];
        float d3 = dh[3] + dm[3] + dl[3];

        float X = __shfl_xor_sync(0xFFFFFFFFu, q ? d0 : d1, 16);
        float Y = __shfl_xor_sync(0xFFFFFFFFu, q ? d2 : d3, 16);
        float zi = (q ? X : d0) + bi_;
        float zf = (q ? d1 : X) + bf_;
        float zg = (q ? Y : d2) + bg_;
        float zo = (q ? d3 : Y) + bo_;

        cst = sigm(zf) * cst + sigm(zi) * tanh_(zg);
        hlast = sigm(zo) * tanh_(cst);

        if (t + 1 < Tt) {
            const int nb = cur ^ 1;
            __half hh, hl;
            splith(hlast, hh, hl);
            Bhi[nb][c][Hh + u] = hh;
            Blo[nb][c][Hh + u] = hl;
            Bhi[nb][lb][lk]     = __ushort_as_half((uint16_t)(p0 & 0xFFFF));
            Blo[nb][lb][lk]     = __ushort_as_half((uint16_t)(p0 >> 16));
            Bhi[nb][lb + 4][lk] = __ushort_as_half((uint16_t)(p1 & 0xFFFF));
            Blo[nb][lb + 4][lk] = __ushort_as_half((uint16_t)(p1 >> 16));
            if (t + 2 < Tt) {
                p0 = g_seq1[((size_t)(t + 2) * Bb + r0 + lb) * Hh + lk];
                p1 = g_seq1[((size_t)(t + 2) * Bb + r0 + lb + 4) * Hh + lk];
            }
        }
        __syncthreads();
    }
    out[(size_t)(r0 + c) * Ee + u] = hlast;
}

extern "C" void kernel_launch(void* const* d_in, const int* in_sizes, int n_in,
                              void* d_out, int out_size)
{
    const float* x    = (const float*)d_in[0];
    const float* Wih1 = (const float*)d_in[1];
    const float* Whh1 = (const float*)d_in[2];
    const float* bih1 = (const float*)d_in[3];
    const float* bhh1 = (const float*)d_in[4];
    const float* Wih2 = (const float*)d_in[5];
    const float* Whh2 = (const float*)d_in[6];
    const float* bih2 = (const float*)d_in[7];
    const float* bhh2 = (const float*)d_in[8];
    float* out = (float*)d_out;

    lstm1_mma<<<128, 512>>>(x, Wih1, Whh1, bih1, bhh1);
    lstm2_mma<<<64, 512>>>(Wih2, Whh2, bih2, bhh2, out);
}